// round 3
// baseline (speedup 1.0000x reference)
#include <cuda_runtime.h>
#include <math.h>
#include <stdint.h>

#define TB 256
#define TT 200
#define TV 16
#define TN 64
#define TG 1024   // V*N
#define TK 1040   // V*(N+1)
#define NCTA 128
#define RTHREADS 256

__device__ float g_xT[TT][TV][TB];
__device__ float g_hsT[TT][TG][TB];
__device__ float g_cT[TG][TB];
__device__ float g_aunT[TT][TV][TB];
__device__ float g_inv[TV][TB];
__device__ float g_gT[TG][TB];
__device__ unsigned g_bar;

typedef unsigned long long ull;
__device__ __forceinline__ ull pk2(float lo, float hi) {
    ull r; asm("mov.b64 %0, {%1, %2};" : "=l"(r) : "f"(lo), "f"(hi)); return r;
}
__device__ __forceinline__ void upk2(ull v, float& lo, float& hi) {
    asm("mov.b64 {%0, %1}, %2;" : "=f"(lo), "=f"(hi) : "l"(v));
}
__device__ __forceinline__ void fma2(ull& d, ull a, ull b) {
    asm("fma.rn.f32x2 %0, %1, %2, %0;" : "+l"(d) : "l"(a), "l"(b));
}

__global__ void k_init() {
    int i = blockIdx.x * blockDim.x + threadIdx.x;
    if (i < TG * TB) ((float*)g_cT)[i] = 0.f;
    if (i == 0) g_bar = 0u;
}

__global__ void k_xT(const float* __restrict__ x) {
    int t = blockIdx.x >> 4, v = blockIdx.x & 15, b = threadIdx.x;
    g_xT[t][v][b] = x[(size_t)b * (TT * TV) + t * TV + v];
}

__global__ void __launch_bounds__(RTHREADS, 1) k_recur(
    const float* __restrict__ U_j, const float* __restrict__ W_j, const float* __restrict__ b_j,
    const float* __restrict__ Wi, const float* __restrict__ bi,
    const float* __restrict__ Wf, const float* __restrict__ bf,
    const float* __restrict__ Wo, const float* __restrict__ bo)
{
    extern __shared__ float sm[];
    float* s_wg = sm;               // [1040][24], row r = gate*8+ul
    float* s_wj = sm + TK * 24;     // [64][8]
    float* s_bg = s_wj + 512;       // 24
    float* s_bj = s_bg + 24;        // 8
    float* s_uu = s_bj + 8;         // 8

    const int tid = threadIdx.x, cta = blockIdx.x;
    const int g0 = cta * 8, v = g0 >> 6, n0 = g0 & 63;

    for (int e = tid; e < TK * 24; e += RTHREADS) {
        int k = e / 24, r = e - k * 24, gate = r >> 3, ul = r & 7;
        const float* W = (gate == 0) ? Wi : (gate == 1) ? Wf : Wo;
        s_wg[e] = W[(size_t)(g0 + ul) * TK + k];
    }
    for (int e = tid; e < 512; e += RTHREADS)
        s_wj[e] = W_j[v * TN * TN + (e >> 3) * TN + (n0 + (e & 7))];
    if (tid < 8) {
        s_bg[tid] = bi[g0 + tid]; s_bg[8 + tid] = bf[g0 + tid]; s_bg[16 + tid] = bo[g0 + tid];
        s_bj[tid] = b_j[v * TN + n0 + tid];
        s_uu[tid] = U_j[v * TN + n0 + tid];
    }
    __syncthreads();

    const int b = tid;
    for (int t = 0; t < TT; ++t) {
        ull acc[12];
        #pragma unroll
        for (int p = 0; p < 12; ++p) {
            int gate = p >> 2, m = p & 3;
            acc[p] = pk2(s_bg[gate * 8 + 2 * m], s_bg[gate * 8 + 2 * m + 1]);
        }
        const float* xt = &g_xT[t][0][0];
        float xv = xt[v * TB + b];
        ull jac[4];
        #pragma unroll
        for (int m = 0; m < 4; ++m)
            jac[m] = pk2(s_bj[2*m] + xv * s_uu[2*m], s_bj[2*m+1] + xv * s_uu[2*m+1]);

        #pragma unroll
        for (int k = 0; k < TV; ++k) {
            float iv = xt[k * TB + b];
            ull dp = pk2(iv, iv);
            const float* wr = s_wg + k * 24;
            #pragma unroll
            for (int q = 0; q < 6; ++q) {
                ulonglong2 w = *reinterpret_cast<const ulonglong2*>(wr + 4 * q);
                fma2(acc[2*q], w.x, dp); fma2(acc[2*q+1], w.y, dp);
            }
        }

        if (t > 0) {
            const float* hp = &g_hsT[t - 1][0][0];
            float nb[8];
            #pragma unroll
            for (int kk = 0; kk < 8; ++kk) nb[kk] = hp[kk * TB + b];
            for (int k = 0; k < TG; k += 8) {
                float cb[8];
                #pragma unroll
                for (int kk = 0; kk < 8; ++kk) cb[kk] = nb[kk];
                if (k + 8 < TG) {
                    #pragma unroll
                    for (int kk = 0; kk < 8; ++kk) nb[kk] = hp[(k + 8 + kk) * TB + b];
                }
                #pragma unroll
                for (int kk = 0; kk < 8; ++kk) {
                    ull dp = pk2(cb[kk], cb[kk]);
                    const float* wr = s_wg + (TV + k + kk) * 24;
                    #pragma unroll
                    for (int q = 0; q < 6; ++q) {
                        ulonglong2 w = *reinterpret_cast<const ulonglong2*>(wr + 4 * q);
                        fma2(acc[2*q], w.x, dp); fma2(acc[2*q+1], w.y, dp);
                    }
                }
            }
            const float* hv = hp + (size_t)v * TN * TB;
            #pragma unroll 8
            for (int m = 0; m < TN; ++m) {
                float iv = hv[m * TB + b];
                ull dp = pk2(iv, iv);
                const float* wr = s_wj + m * 8;
                ulonglong2 w0 = *reinterpret_cast<const ulonglong2*>(wr);
                ulonglong2 w1 = *reinterpret_cast<const ulonglong2*>(wr + 4);
                fma2(jac[0], w0.x, dp); fma2(jac[1], w0.y, dp);
                fma2(jac[2], w1.x, dp); fma2(jac[3], w1.y, dp);
            }
        }

        float* ct = &g_cT[0][0];
        float* ho = &g_hsT[t][0][0];
        #pragma unroll
        for (int ul = 0; ul < 8; ++ul) {
            int m = ul >> 1;
            float z0, z1, zi, zf, zo, zj;
            upk2(acc[m], z0, z1);     zi = (ul & 1) ? z1 : z0;
            upk2(acc[4+m], z0, z1);   zf = (ul & 1) ? z1 : z0;
            upk2(acc[8+m], z0, z1);   zo = (ul & 1) ? z1 : z0;
            upk2(jac[m], z0, z1);     zj = (ul & 1) ? z1 : z0;
            float iv = 1.f / (1.f + expf(-zi));
            float fv = 1.f / (1.f + expf(-zf));
            float ov = 1.f / (1.f + expf(-zo));
            float jv = tanhf(zj);
            size_t idx = (size_t)(g0 + ul) * TB + b;
            float cn = ct[idx] * fv + iv * jv;
            ct[idx] = cn;
            ho[idx] = ov * tanhf(cn);
        }

        __syncthreads();
        if (tid == 0) {
            __threadfence();
            atomicAdd(&g_bar, 1u);
            unsigned target = (unsigned)(t + 1) * gridDim.x;
            while (*((volatile unsigned*)&g_bar) < target) { }
            __threadfence();
        }
        __syncthreads();
    }
}

__global__ void k_alphaA(const float* __restrict__ Fa, const float* __restrict__ Fab) {
    __shared__ float fa[TN]; __shared__ float fabv;
    int v = blockIdx.x, t0 = blockIdx.y * (TT / 8), b = threadIdx.x;
    if (threadIdx.x < TN) fa[threadIdx.x] = Fa[v * TN + threadIdx.x];
    if (threadIdx.x == 0) fabv = Fab[v];
    __syncthreads();
    for (int t = t0; t < t0 + TT / 8; ++t) {
        const float* hr = &g_hsT[t][v * TN][0];
        float ap = fabv;
        #pragma unroll 8
        for (int n = 0; n < TN; ++n) ap += hr[n * TB + b] * fa[n];
        g_aunT[t][v][b] = expf(tanhf(ap));
    }
}

__global__ void k_alphaInv() {
    int v = blockIdx.x, b = threadIdx.x;
    float s = 0.f;
    for (int t = 0; t < TT; ++t) s += g_aunT[t][v][b];
    g_inv[v][b] = 1.f / s;
}

__global__ void k_gn() {
    int v = blockIdx.x, nc = blockIdx.y * 4, b = threadIdx.x;
    float a0 = 0.f, a1 = 0.f, a2 = 0.f, a3 = 0.f;
    for (int t = 0; t < TT; ++t) {
        float au = g_aunT[t][v][b];
        const float* hr = &g_hsT[t][v * TN + nc][0];
        a0 += au * hr[0 * TB + b]; a1 += au * hr[1 * TB + b];
        a2 += au * hr[2 * TB + b]; a3 += au * hr[3 * TB + b];
    }
    float inv = g_inv[v][b];
    g_gT[v*TN+nc+0][b] = a0*inv; g_gT[v*TN+nc+1][b] = a1*inv;
    g_gT[v*TN+nc+2][b] = a2*inv; g_gT[v*TN+nc+3][b] = a3*inv;
}

__global__ void k_alphaOut(float* __restrict__ out) {
    int t = blockIdx.x, b = threadIdx.x;
    float* ao = out + TB;
    #pragma unroll
    for (int v = 0; v < TV; ++v)
        ao[((size_t)b * TT + t) * TV + v] = g_aunT[t][v][b] * g_inv[v][b];
}

__global__ void k_final(const float* __restrict__ Fbw, const float* __restrict__ Fbb,
                        const float* __restrict__ Phw, const float* __restrict__ Phb,
                        float* __restrict__ out) {
    __shared__ float phi[2 * TN], fbw[2 * TN];
    __shared__ float phib, fbb;
    int b = threadIdx.x;
    if (threadIdx.x < 2 * TN) { phi[threadIdx.x] = Phw[threadIdx.x]; fbw[threadIdx.x] = Fbw[threadIdx.x]; }
    if (threadIdx.x == 0) { phib = Phb[0]; fbb = Fbb[0]; }
    __syncthreads();
    float mu[TV], bu[TV], bs = 0.f;
    #pragma unroll
    for (int v = 0; v < TV; ++v) {
        const float* gr = &g_gT[v * TN][0];
        const float* hr = &g_hsT[TT - 1][v * TN][0];
        float m_ = phib, p_ = fbb;
        #pragma unroll 8
        for (int n = 0; n < TN; ++n) {
            float gv = gr[n * TB + b], hv = hr[n * TB + b];
            m_ += gv * phi[n] + hv * phi[TN + n];
            p_ += gv * fbw[n] + hv * fbw[TN + n];
        }
        mu[v] = m_;
        float e = expf(tanhf(p_));
        bu[v] = e; bs += e;
    }
    float ib = 1.f / bs, mean = 0.f;
    float* bout = out + TB + (size_t)TB * TT * TV;
    #pragma unroll
    for (int v = 0; v < TV; ++v) {
        float be = bu[v] * ib;
        mean += be * mu[v];
        bout[(size_t)b * TV + v] = be;
    }
    out[b] = mean;
}

extern "C" void kernel_launch(void* const* d_in, const int* in_sizes, int n_in,
                              void* d_out, int out_size) {
    const float* x    = (const float*)d_in[0];
    const float* U_j  = (const float*)d_in[1];
    const float* W_j  = (const float*)d_in[2];
    const float* b_j  = (const float*)d_in[3];
    const float* Wi   = (const float*)d_in[4];
    const float* bi   = (const float*)d_in[5];
    const float* Wf   = (const float*)d_in[6];
    const float* bf   = (const float*)d_in[7];
    const float* Wo   = (const float*)d_in[8];
    const float* bo   = (const float*)d_in[9];
    const float* Fa   = (const float*)d_in[10];
    const float* Fab  = (const float*)d_in[11];
    const float* Fbw  = (const float*)d_in[12];
    const float* Fbb  = (const float*)d_in[13];
    const float* Phw  = (const float*)d_in[14];
    const float* Phb  = (const float*)d_in[15];
    float* out = (float*)d_out;

    static const size_t SMEM = (size_t)(TK * 24 + 512 + 24 + 8 + 8) * sizeof(float);
    cudaFuncSetAttribute(k_recur, cudaFuncAttributeMaxDynamicSharedMemorySize, (int)SMEM);

    k_init<<<(TG * TB + 255) / 256, 256>>>();
    k_xT<<<TT * TV, TB>>>(x);
    k_recur<<<NCTA, RTHREADS, SMEM>>>(U_j, W_j, b_j, Wi, bi, Wf, bf, Wo, bo);
    k_alphaA<<<dim3(TV, 8), TB>>>(Fa, Fab);
    k_alphaInv<<<TV, TB>>>();
    k_gn<<<dim3(TV, TV), TB>>>();
    k_alphaOut<<<TT, TB>>>(out);
    k_final<<<1, TB>>>(Fbw, Fbb, Phw, Phb, out);
}